// round 14
// baseline (speedup 1.0000x reference)
#include <cuda_runtime.h>
#include <cuda_bf16.h>
#include <cuda_fp16.h>
#include <math.h>
#include <stdint.h>

#define B_ 8
#define T_ 2048
#define D_ 1024
#define H_ 128
#define SCALE2 0.12751763226289247f   // log2(e)/sqrt(128)
#define MASKV  (-1e30f)

__device__ __forceinline__ uint32_t smem_u32(const void* p) {
    uint32_t a;
    asm("{ .reg .u64 t; cvta.to.shared.u64 t, %1; cvt.u32.u64 %0, t; }"
        : "=r"(a) : "l"(p));
    return a;
}
__device__ __forceinline__ uint32_t pack_h2(float a, float b) {
    __half2 t = __floats2half2_rn(a, b);
    return *reinterpret_cast<uint32_t*>(&t);
}

#define CP16(dst, src) \
    asm volatile("cp.async.cg.shared.global [%0], [%1], 16;" \
                 :: "r"(dst), "l"(src) : "memory")
#define CP_COMMIT() asm volatile("cp.async.commit_group;" ::: "memory")
#define CP_WAIT0()  asm volatile("cp.async.wait_group 0;" ::: "memory")
#define CP_WAIT1()  asm volatile("cp.async.wait_group 1;" ::: "memory")

#define LDSM4(r0, r1, r2, r3, addr) \
    asm volatile("ldmatrix.sync.aligned.m8n8.x4.shared.b16 {%0,%1,%2,%3}, [%4];" \
                 : "=r"(r0), "=r"(r1), "=r"(r2), "=r"(r3) : "r"(addr))
#define LDSM4T(r0, r1, r2, r3, addr) \
    asm volatile("ldmatrix.sync.aligned.m8n8.x4.trans.shared.b16 {%0,%1,%2,%3}, [%4];" \
                 : "=r"(r0), "=r"(r1), "=r"(r2), "=r"(r3) : "r"(addr))

#define MMA16816H(d, a, b) \
    asm volatile("mma.sync.aligned.m16n8k16.row.col.f32.f16.f16.f32 " \
                 "{%0,%1,%2,%3},{%4,%5,%6,%7},{%8,%9},{%0,%1,%2,%3};" \
                 : "+f"((d)[0]), "+f"((d)[1]), "+f"((d)[2]), "+f"((d)[3]) \
                 : "r"((a)[0]), "r"((a)[1]), "r"((a)[2]), "r"((a)[3]), \
                   "r"((b)[0]), "r"((b)[1]))

// ---- device scratch (all fp16) ----
__device__ __half g_q_hi[(size_t)B_ * T_ * H_];
__device__ __half g_q_lo[(size_t)B_ * T_ * H_];
__device__ __half g_k_hi[(size_t)B_ * T_ * H_];
__device__ __half g_v_hi[(size_t)B_ * T_ * H_];
__device__ __half g_Wb_hi[384 * 1024];
__device__ __half g_x_hi[(size_t)B_ * T_ * D_];
__device__ __half g_x_lo[(size_t)B_ * T_ * D_];

// ---------------------------------------------------------------------------
// Fused prep, MLP=4: X -> fp16 hi/lo; Wcat -> fp16 hi only.
// ---------------------------------------------------------------------------
__global__ __launch_bounds__(256) void prep_kernel(
    const float* __restrict__ x,
    const float* __restrict__ Wq,
    const float* __restrict__ Wk,
    const float* __restrict__ Wv)
{
    if (blockIdx.x < 4096) {
        const size_t base = (size_t)blockIdx.x * 1024 + threadIdx.x;
        float4 f[4];
#pragma unroll
        for (int k = 0; k < 4; k++) f[k] = ((const float4*)x)[base + k * 256];
#pragma unroll
        for (int k = 0; k < 4; k++) {
            __half h0 = __float2half_rn(f[k].x);
            __half h1 = __float2half_rn(f[k].y);
            __half h2 = __float2half_rn(f[k].z);
            __half h3 = __float2half_rn(f[k].w);
            uint2 hv, lv;
            hv.x = (uint32_t)__half_as_ushort(h0) |
                   ((uint32_t)__half_as_ushort(h1) << 16);
            hv.y = (uint32_t)__half_as_ushort(h2) |
                   ((uint32_t)__half_as_ushort(h3) << 16);
            lv.x = pack_h2(f[k].x - __half2float(h0), f[k].y - __half2float(h1));
            lv.y = pack_h2(f[k].z - __half2float(h2), f[k].w - __half2float(h3));
            ((uint2*)g_x_hi)[base + k * 256] = hv;
            ((uint2*)g_x_lo)[base + k * 256] = lv;
        }
    } else {
        const int n = blockIdx.x - 4096;
        const float* W = (n < 128) ? Wq : (n < 256 ? Wk : Wv);
        const int h = n & 127;
        for (int k = threadIdx.x; k < 1024; k += 256) {
            g_Wb_hi[(size_t)n * 1024 + k] = __float2half_rn(W[(size_t)k * H_ + h]);
        }
    }
}

// ---------------------------------------------------------------------------
// QKV GEMM: fp16 2-term ((xh+xl) x w_hi). CTA 128x64, 256 thr, warps 4x2,
// 2 CTAs/SM. Stage: AH 0 (16K) | AL 16K (16K) | BH 32K (8K) = 40KB.
// ---------------------------------------------------------------------------
#define QSTG 40960
#define QK_SMEM (2 * QSTG)

__device__ __forceinline__ void qkv_issue(uint32_t dstbase, int m0, int n0,
                                          int k0, int tid)
{
#pragma unroll
    for (int i = 0; i < 4; i++) {
        int idx = i * 256 + tid;
        int r = idx >> 3, g = idx & 7;
        uint32_t off = (uint32_t)(r * 128 + ((g ^ (r & 7)) << 4));
        const size_t ax = (size_t)(m0 + r) * D_ + k0 + g * 8;
        CP16(dstbase + off,         g_x_hi + ax);
        CP16(dstbase + 16384 + off, g_x_lo + ax);
    }
#pragma unroll
    for (int i = 0; i < 2; i++) {
        int idx = i * 256 + tid;
        int r = idx >> 3, g = idx & 7;
        uint32_t off = (uint32_t)(r * 128 + ((g ^ (r & 7)) << 4));
        const size_t bx = (size_t)(n0 + r) * D_ + k0 + g * 8;
        CP16(dstbase + 32768 + off, g_Wb_hi + bx);
    }
}

__global__ __launch_bounds__(256, 2) void qkv_mma_kernel()
{
    extern __shared__ char smq[];
    const uint32_t sb = smem_u32(smq);
    const int tid  = threadIdx.x;
    const int lane = tid & 31, warp = tid >> 5;
    const int wm = warp >> 1, wn = warp & 1;
    const int m0 = blockIdx.y * 128;
    const int n0 = blockIdx.x * 64;

    float acc[2][4][4];
#pragma unroll
    for (int mt = 0; mt < 2; mt++)
#pragma unroll
        for (int nt = 0; nt < 4; nt++)
#pragma unroll
            for (int j = 0; j < 4; j++) acc[mt][nt][j] = 0.f;

    uint32_t a_rb[2], a_xr[2];
#pragma unroll
    for (int mt = 0; mt < 2; mt++) {
        int rowA = wm * 32 + mt * 16 + (lane & 15);
        a_rb[mt] = (uint32_t)(rowA * 128);
        a_xr[mt] = (uint32_t)((rowA & 7) << 4);
    }
    const uint32_t a_cb = (uint32_t)((lane >> 4) * 16);
    uint32_t b_rb[2], b_xr[2];
#pragma unroll
    for (int p = 0; p < 2; p++) {
        int nB = wn * 32 + p * 16 + ((lane >> 4) << 3) + (lane & 7);
        b_rb[p] = (uint32_t)(nB * 128);
        b_xr[p] = (uint32_t)((nB & 7) << 4);
    }
    const uint32_t b_cb = (uint32_t)(((lane >> 3) & 1) * 16);

    qkv_issue(sb, m0, n0, 0, tid);
    CP_COMMIT();

    for (int kc = 0; kc < 16; kc++) {
        if (kc < 15) {
            qkv_issue(sb + (uint32_t)(((kc + 1) & 1) * QSTG),
                      m0, n0, (kc + 1) * 64, tid);
            CP_COMMIT();
            CP_WAIT1();
        } else {
            CP_WAIT0();
        }
        __syncthreads();

        const uint32_t bufb = sb + (uint32_t)((kc & 1) * QSTG);
#pragma unroll
        for (int ks = 0; ks < 4; ks++) {
            const uint32_t acol = (a_cb + ks * 32);
            const uint32_t bcol = (b_cb + ks * 32);
            uint32_t ah[2][4], al[2][4];
#pragma unroll
            for (int mt = 0; mt < 2; mt++) {
                LDSM4(ah[mt][0], ah[mt][1], ah[mt][2], ah[mt][3],
                      bufb + a_rb[mt] + (acol ^ a_xr[mt]));
                LDSM4(al[mt][0], al[mt][1], al[mt][2], al[mt][3],
                      bufb + 16384 + a_rb[mt] + (acol ^ a_xr[mt]));
            }
            uint32_t bh[4][2];
#pragma unroll
            for (int p = 0; p < 2; p++) {
                uint32_t r0, r1, r2, r3;
                LDSM4(r0, r1, r2, r3, bufb + 32768 + b_rb[p] + (bcol ^ b_xr[p]));
                bh[2 * p][0] = r0; bh[2 * p][1] = r1;
                bh[2 * p + 1][0] = r2; bh[2 * p + 1][1] = r3;
            }
#pragma unroll
            for (int mt = 0; mt < 2; mt++)
#pragma unroll
                for (int nt = 0; nt < 4; nt++) {
                    MMA16816H(acc[mt][nt], ah[mt], bh[nt]);
                    MMA16816H(acc[mt][nt], al[mt], bh[nt]);
                }
        }
        __syncthreads();
    }

    // ---- epilogue: fp16 outputs. Q: hi+lo, K/V: hi only. ----
    const int sel = n0 >> 7;
    __half* oh = (sel == 0) ? g_q_hi : (sel == 1 ? g_k_hi : g_v_hi);
    const int colbase = n0 & 127;
    const int g = lane >> 2, tig = lane & 3;
#pragma unroll
    for (int mt = 0; mt < 2; mt++) {
        const int row0 = m0 + wm * 32 + mt * 16 + g;
#pragma unroll
        for (int nt = 0; nt < 4; nt++) {
            const int col = colbase + wn * 32 + nt * 8 + tig * 2;
#pragma unroll
            for (int h = 0; h < 2; h++) {
                const int row = row0 + h * 8;
                float a0 = acc[mt][nt][2 * h], a1 = acc[mt][nt][2 * h + 1];
                __half h0 = __float2half_rn(a0);
                __half h1 = __float2half_rn(a1);
                uint32_t hv = (uint32_t)__half_as_ushort(h0) |
                              ((uint32_t)__half_as_ushort(h1) << 16);
                *(uint32_t*)(oh + (size_t)row * H_ + col) = hv;
                if (sel == 0) {
                    *(uint32_t*)(g_q_lo + (size_t)row * H_ + col) =
                        pack_h2(a0 - __half2float(h0), a1 - __half2float(h1));
                }
            }
        }
    }
}

// ---------------------------------------------------------------------------
// Flash attention: S = (qh+ql) x k_hi (2-term); O += P_hi x V_hi (1-term).
// 256 threads, 4 row-groups x 2 col-halves, KV stage 32KB, 2 barriers/tile.
// ---------------------------------------------------------------------------
#define AQH 0
#define AQL 16384
#define AKV0 32768
#define KVBUF 32768
#define AEXM 98304
#define AEXS 98816
#define ATT_SMEM 99328

__device__ __forceinline__ void kv_issue256(uint32_t dstbase, size_t kbase, int tid)
{
#pragma unroll
    for (int i = 0; i < 4; i++) {
        int idx = i * 256 + tid;
        int r = idx >> 4, gq = idx & 15;
        uint32_t off = (uint32_t)(r * 256 + ((gq ^ (r & 7)) << 4));
        const size_t ge = kbase + (size_t)r * 128 + gq * 8;
        CP16(dstbase + off,         g_k_hi + ge);
        CP16(dstbase + 16384 + off, g_v_hi + ge);
    }
}

__global__ __launch_bounds__(256, 1) void attn_mma_kernel(float* __restrict__ out)
{
    extern __shared__ char smA[];
    const uint32_t sb = smem_u32(smA);
    float* mPart = (float*)(smA + AEXM);
    float* sPart = (float*)(smA + AEXS);

    const int tid  = threadIdx.x;
    const int lane = tid & 31, warp = tid >> 5;
    const int wr = warp & 3;
    const int wh = warp >> 2;
    const int b    = blockIdx.y;
    const int g4   = lane >> 2, tig = lane & 3;
    const int b3   = (lane >> 3) & 1;
    const int rk   = ((lane >> 4) << 3) + (lane & 7);
    const int xr7  = lane & 7;

    const int qrow = wr * 16 + (lane & 15);
    const uint32_t q_rb = (uint32_t)(qrow * 256);
    const uint32_t q_xr = (uint32_t)((qrow & 7));

    for (int pass = 0; pass < 2; pass++) {
        const int qt = pass ? (31 - (int)blockIdx.x) : (int)blockIdx.x;
        const size_t qbase = ((size_t)b * T_ + (size_t)qt * 64) * H_;
        const size_t batchbase = (size_t)b * T_ * H_;

        __syncthreads();
        kv_issue256(sb + AKV0, batchbase, tid);
        CP_COMMIT();

#pragma unroll
        for (int i = 0; i < 4; i++) {
            int idx = i * 256 + tid;
            int r = idx >> 4, gq = idx & 15;
            uint32_t off = (uint32_t)(r * 256 + ((gq ^ (r & 7)) << 4));
            *(uint4*)(smA + AQH + off) = *(const uint4*)(g_q_hi + qbase + r * 128 + gq * 8);
            *(uint4*)(smA + AQL + off) = *(const uint4*)(g_q_lo + qbase + r * 128 + gq * 8);
        }

        float oacc[16][4];
#pragma unroll
        for (int t = 0; t < 16; t++)
#pragma unroll
            for (int j = 0; j < 4; j++) oacc[t][j] = 0.f;
        float m0 = MASKV, m1 = MASKV, l0 = 0.f, l1 = 0.f;

        const int r0 = wr * 16 + g4, r1 = r0 + 8;

        for (int kt = 0; kt <= qt; kt++) {
            CP_WAIT0();
            __syncthreads();
            const uint32_t kvb = sb + AKV0 + (uint32_t)((kt & 1) * KVBUF);

            float sacc[4][4];
#pragma unroll
            for (int nt = 0; nt < 4; nt++)
#pragma unroll
                for (int j = 0; j < 4; j++) sacc[nt][j] = 0.f;

#pragma unroll
            for (int ks = 0; ks < 8; ks++) {
                uint32_t qh[4], ql[4];
                {
                    int gq = ks * 2 + (lane >> 4);
                    uint32_t off = q_rb + (uint32_t)((gq ^ q_xr) << 4);
                    LDSM4(qh[0], qh[1], qh[2], qh[3], sb + AQH + off);
                    LDSM4(ql[0], ql[1], ql[2], ql[3], sb + AQL + off);
                }
                const int gq = ks * 2 + b3;
                const uint32_t csw = (uint32_t)((gq ^ xr7) << 4);
#pragma unroll
                for (int p = 0; p < 2; p++) {
                    const uint32_t off =
                        (uint32_t)((wh * 32 + p * 16 + rk) * 256) + csw;
                    uint32_t h0, h1, h2, h3;
                    LDSM4(h0, h1, h2, h3, kvb + off);
                    uint32_t bh0[2] = {h0, h1}, bh1[2] = {h2, h3};
                    MMA16816H(sacc[2 * p],     qh, bh0);
                    MMA16816H(sacc[2 * p],     ql, bh0);
                    MMA16816H(sacc[2 * p + 1], qh, bh1);
                    MMA16816H(sacc[2 * p + 1], ql, bh1);
                }
            }

#pragma unroll
            for (int nt = 0; nt < 4; nt++)
#pragma unroll
                for (int j = 0; j < 4; j++) sacc[nt][j] *= SCALE2;
            if (kt == qt) {
#pragma unroll
                for (int nt = 0; nt < 4; nt++) {
                    const int c0 = wh * 32 + nt * 8 + tig * 2, c1 = c0 + 1;
                    if (c0 > r0) sacc[nt][0] = MASKV;
                    if (c1 > r0) sacc[nt][1] = MASKV;
                    if (c0 > r1) sacc[nt][2] = MASKV;
                    if (c1 > r1) sacc[nt][3] = MASKV;
                }
            }

            float rm0 = MASKV, rm1 = MASKV;
#pragma unroll
            for (int nt = 0; nt < 4; nt++) {
                rm0 = fmaxf(rm0, fmaxf(sacc[nt][0], sacc[nt][1]));
                rm1 = fmaxf(rm1, fmaxf(sacc[nt][2], sacc[nt][3]));
            }
            rm0 = fmaxf(rm0, __shfl_xor_sync(0xffffffffu, rm0, 1));
            rm0 = fmaxf(rm0, __shfl_xor_sync(0xffffffffu, rm0, 2));
            rm1 = fmaxf(rm1, __shfl_xor_sync(0xffffffffu, rm1, 1));
            rm1 = fmaxf(rm1, __shfl_xor_sync(0xffffffffu, rm1, 2));
            if (tig == 0) {
                mPart[wh * 64 + r0] = rm0;
                mPart[wh * 64 + r1] = rm1;
            }

            float rs0 = 0.f, rs1 = 0.f;
#pragma unroll
            for (int nt = 0; nt < 4; nt++) {
                float p0 = exp2f(sacc[nt][0] - rm0);
                float p1 = exp2f(sacc[nt][1] - rm0);
                float p2 = exp2f(sacc[nt][2] - rm1);
                float p3 = exp2f(sacc[nt][3] - rm1);
                sacc[nt][0] = p0; sacc[nt][1] = p1;
                sacc[nt][2] = p2; sacc[nt][3] = p3;
                rs0 += p0 + p1; rs1 += p2 + p3;
            }
            rs0 += __shfl_xor_sync(0xffffffffu, rs0, 1);
            rs0 += __shfl_xor_sync(0xffffffffu, rs0, 2);
            rs1 += __shfl_xor_sync(0xffffffffu, rs1, 1);
            rs1 += __shfl_xor_sync(0xffffffffu, rs1, 2);
            if (tig == 0) {
                sPart[wh * 64 + r0] = rs0;
                sPart[wh * 64 + r1] = rs1;
            }
            __syncthreads();

            if (kt < qt) {
                kv_issue256(sb + AKV0 + (uint32_t)(((kt + 1) & 1) * KVBUF),
                            batchbase + (size_t)(kt + 1) * 64 * H_, tid);
                CP_COMMIT();
            }

            const float rmA0 = mPart[r0], rmB0 = mPart[64 + r0];
            const float rmA1 = mPart[r1], rmB1 = mPart[64 + r1];
            const float mn0 = fmaxf(m0, fmaxf(rmA0, rmB0));
            const float mn1 = fmaxf(m1, fmaxf(rmA1, rmB1));
            const float corr0 = exp2f(m0 - mn0), corr1 = exp2f(m1 - mn1);
            l0 = l0 * corr0 + sPart[r0]      * exp2f(rmA0 - mn0)
                            + sPart[64 + r0] * exp2f(rmB0 - mn0);
            l1 = l1 * corr1 + sPart[r1]      * exp2f(rmA1 - mn1)
                            + sPart[64 + r1] * exp2f(rmB1 - mn1);
            m0 = mn0; m1 = mn1;
            const float fac0 = exp2f(rm0 - mn0);
            const float fac1 = exp2f(rm1 - mn1);

#pragma unroll
            for (int t = 0; t < 16; t++) {
                oacc[t][0] *= corr0; oacc[t][1] *= corr0;
                oacc[t][2] *= corr1; oacc[t][3] *= corr1;
            }

            // ---- P fp16 fragments (hi only, rescale folded) ----
            uint32_t ph[2][4];
#pragma unroll
            for (int c = 0; c < 2; c++) {
#pragma unroll
                for (int half = 0; half < 2; half++) {
                    const int nt = 2 * c + half;
                    ph[c][2 * half] =
                        pack_h2(sacc[nt][0] * fac0, sacc[nt][1] * fac0);
                    ph[c][2 * half + 1] =
                        pack_h2(sacc[nt][2] * fac1, sacc[nt][3] * fac1);
                }
            }

            // ---- O += P_hi x V_hi ----
#pragma unroll
            for (int c = 0; c < 2; c++) {
                const uint32_t roff = (uint32_t)(((wh * 2 + c) * 16 + rk) * 256);
#pragma unroll
                for (int jp = 0; jp < 8; jp++) {
                    const int gq = jp * 2 + b3;
                    const uint32_t off = roff + (uint32_t)((gq ^ xr7) << 4);
                    uint32_t t0, t1, t2, t3;
                    LDSM4T(t0, t1, t2, t3, kvb + 16384 + off);
                    uint32_t vh0[2] = {t0, t2}, vh1[2] = {t1, t3};
                    MMA16816H(oacc[2 * jp],     ph[c], vh0);
                    MMA16816H(oacc[2 * jp + 1], ph[c], vh1);
                }
            }
        }

        __syncthreads();
        if (wh == 1) {
            float* buf = (float*)(smA + AKV0 + wr * 8192);
#pragma unroll
            for (int t = 0; t < 16; t++) {
                const int col = t * 8 + tig * 2;
                *(float2*)&buf[g4 * 128 + col] =
                    make_float2(oacc[t][0], oacc[t][1]);
                *(float2*)&buf[(g4 + 8) * 128 + col] =
                    make_float2(oacc[t][2], oacc[t][3]);
            }
        }
        __syncthreads();
        if (wh == 0) {
            const float* buf = (const float*)(smA + AKV0 + wr * 8192);
            const float inv0 = 1.f / l0, inv1 = 1.f / l1;
#pragma unroll
            for (int t = 0; t < 16; t++) {
                const int col = t * 8 + tig * 2;
                float2 p0 = *(const float2*)&buf[g4 * 128 + col];
                float2 p1 = *(const float2*)&buf[(g4 + 8) * 128 + col];
                *(float2*)(out + qbase + (size_t)r0 * H_ + col) =
                    make_float2((oacc[t][0] + p0.x) * inv0,
                                (oacc[t][1] + p0.y) * inv0);
                *(float2*)(out + qbase + (size_t)r1 * H_ + col) =
                    make_float2((oacc[t][2] + p1.x) * inv1,
                                (oacc[t][3] + p1.y) * inv1);
            }
        }
    }
}

// ---------------------------------------------------------------------------
extern "C" void kernel_launch(void* const* d_in, const int* in_sizes, int n_in,
                              void* d_out, int out_size)
{
    const float* x  = (const float*)d_in[0];
    const float* Wq = (const float*)d_in[1];
    const float* Wk = (const float*)d_in[2];
    const float* Wv = (const float*)d_in[3];
    float* out = (float*)d_out;

    prep_kernel<<<4480, 256>>>(x, Wq, Wk, Wv);

    cudaFuncSetAttribute(qkv_mma_kernel,
                         cudaFuncAttributeMaxDynamicSharedMemorySize, QK_SMEM);
    qkv_mma_kernel<<<dim3(6, 128), 256, QK_SMEM>>>();

    cudaFuncSetAttribute(attn_mma_kernel,
                         cudaFuncAttributeMaxDynamicSharedMemorySize, ATT_SMEM);
    attn_mma_kernel<<<dim3(16, 8), 256, ATT_SMEM>>>(out);
}

// round 15
// speedup vs baseline: 1.4731x; 1.4731x over previous
#include <cuda_runtime.h>
#include <cuda_bf16.h>
#include <cuda_fp16.h>
#include <math.h>
#include <stdint.h>

#define B_ 8
#define T_ 2048
#define D_ 1024
#define H_ 128
#define SCALE2 0.12751763226289247f   // log2(e)/sqrt(128)
#define MASKV  (-1e30f)

__device__ __forceinline__ uint32_t smem_u32(const void* p) {
    uint32_t a;
    asm("{ .reg .u64 t; cvta.to.shared.u64 t, %1; cvt.u32.u64 %0, t; }"
        : "=r"(a) : "l"(p));
    return a;
}
__device__ __forceinline__ uint32_t pack_h2(float a, float b) {
    __half2 t = __floats2half2_rn(a, b);
    return *reinterpret_cast<uint32_t*>(&t);
}

#define CP16(dst, src) \
    asm volatile("cp.async.cg.shared.global [%0], [%1], 16;" \
                 :: "r"(dst), "l"(src) : "memory")
#define CP_COMMIT() asm volatile("cp.async.commit_group;" ::: "memory")
#define CP_WAIT0()  asm volatile("cp.async.wait_group 0;" ::: "memory")
#define CP_WAIT1()  asm volatile("cp.async.wait_group 1;" ::: "memory")

#define LDSM4(r0, r1, r2, r3, addr) \
    asm volatile("ldmatrix.sync.aligned.m8n8.x4.shared.b16 {%0,%1,%2,%3}, [%4];" \
                 : "=r"(r0), "=r"(r1), "=r"(r2), "=r"(r3) : "r"(addr))
#define LDSM4T(r0, r1, r2, r3, addr) \
    asm volatile("ldmatrix.sync.aligned.m8n8.x4.trans.shared.b16 {%0,%1,%2,%3}, [%4];" \
                 : "=r"(r0), "=r"(r1), "=r"(r2), "=r"(r3) : "r"(addr))

#define MMA16816H(d, a, b) \
    asm volatile("mma.sync.aligned.m16n8k16.row.col.f32.f16.f16.f32 " \
                 "{%0,%1,%2,%3},{%4,%5,%6,%7},{%8,%9},{%0,%1,%2,%3};" \
                 : "+f"((d)[0]), "+f"((d)[1]), "+f"((d)[2]), "+f"((d)[3]) \
                 : "r"((a)[0]), "r"((a)[1]), "r"((a)[2]), "r"((a)[3]), \
                   "r"((b)[0]), "r"((b)[1]))

// ---- device scratch (all fp16) ----
__device__ __half g_q_hi[(size_t)B_ * T_ * H_];
__device__ __half g_q_lo[(size_t)B_ * T_ * H_];
__device__ __half g_k_hi[(size_t)B_ * T_ * H_];
__device__ __half g_v_hi[(size_t)B_ * T_ * H_];
__device__ __half g_Wb_hi[384 * 1024];
__device__ __half g_x_hi[(size_t)B_ * T_ * D_];
__device__ __half g_x_lo[(size_t)B_ * T_ * D_];

// ---------------------------------------------------------------------------
// Fused prep, MLP=4: X -> fp16 hi/lo; Wcat -> fp16 hi only.
// ---------------------------------------------------------------------------
__global__ __launch_bounds__(256) void prep_kernel(
    const float* __restrict__ x,
    const float* __restrict__ Wq,
    const float* __restrict__ Wk,
    const float* __restrict__ Wv)
{
    if (blockIdx.x < 4096) {
        const size_t base = (size_t)blockIdx.x * 1024 + threadIdx.x;
        float4 f[4];
#pragma unroll
        for (int k = 0; k < 4; k++) f[k] = ((const float4*)x)[base + k * 256];
#pragma unroll
        for (int k = 0; k < 4; k++) {
            __half h0 = __float2half_rn(f[k].x);
            __half h1 = __float2half_rn(f[k].y);
            __half h2 = __float2half_rn(f[k].z);
            __half h3 = __float2half_rn(f[k].w);
            uint2 hv, lv;
            hv.x = (uint32_t)__half_as_ushort(h0) |
                   ((uint32_t)__half_as_ushort(h1) << 16);
            hv.y = (uint32_t)__half_as_ushort(h2) |
                   ((uint32_t)__half_as_ushort(h3) << 16);
            lv.x = pack_h2(f[k].x - __half2float(h0), f[k].y - __half2float(h1));
            lv.y = pack_h2(f[k].z - __half2float(h2), f[k].w - __half2float(h3));
            ((uint2*)g_x_hi)[base + k * 256] = hv;
            ((uint2*)g_x_lo)[base + k * 256] = lv;
        }
    } else {
        const int n = blockIdx.x - 4096;
        const float* W = (n < 128) ? Wq : (n < 256 ? Wk : Wv);
        const int h = n & 127;
        for (int k = threadIdx.x; k < 1024; k += 256) {
            g_Wb_hi[(size_t)n * 1024 + k] = __float2half_rn(W[(size_t)k * H_ + h]);
        }
    }
}

// ---------------------------------------------------------------------------
// QKV GEMM: fp16 2-term ((xh+xl) x w_hi). CTA 128x64, 256 thr, warps 4x2,
// 2 CTAs/SM. Stage: AH 0 (16K) | AL 16K (16K) | BH 32K (8K) = 40KB.
// ---------------------------------------------------------------------------
#define QSTG 40960
#define QK_SMEM (2 * QSTG)

__device__ __forceinline__ void qkv_issue(uint32_t dstbase, int m0, int n0,
                                          int k0, int tid)
{
#pragma unroll
    for (int i = 0; i < 4; i++) {
        int idx = i * 256 + tid;
        int r = idx >> 3, g = idx & 7;
        uint32_t off = (uint32_t)(r * 128 + ((g ^ (r & 7)) << 4));
        const size_t ax = (size_t)(m0 + r) * D_ + k0 + g * 8;
        CP16(dstbase + off,         g_x_hi + ax);
        CP16(dstbase + 16384 + off, g_x_lo + ax);
    }
#pragma unroll
    for (int i = 0; i < 2; i++) {
        int idx = i * 256 + tid;
        int r = idx >> 3, g = idx & 7;
        uint32_t off = (uint32_t)(r * 128 + ((g ^ (r & 7)) << 4));
        const size_t bx = (size_t)(n0 + r) * D_ + k0 + g * 8;
        CP16(dstbase + 32768 + off, g_Wb_hi + bx);
    }
}

__global__ __launch_bounds__(256, 2) void qkv_mma_kernel()
{
    extern __shared__ char smq[];
    const uint32_t sb = smem_u32(smq);
    const int tid  = threadIdx.x;
    const int lane = tid & 31, warp = tid >> 5;
    const int wm = warp >> 1, wn = warp & 1;
    const int m0 = blockIdx.y * 128;
    const int n0 = blockIdx.x * 64;

    float acc[2][4][4];
#pragma unroll
    for (int mt = 0; mt < 2; mt++)
#pragma unroll
        for (int nt = 0; nt < 4; nt++)
#pragma unroll
            for (int j = 0; j < 4; j++) acc[mt][nt][j] = 0.f;

    uint32_t a_rb[2], a_xr[2];
#pragma unroll
    for (int mt = 0; mt < 2; mt++) {
        int rowA = wm * 32 + mt * 16 + (lane & 15);
        a_rb[mt] = (uint32_t)(rowA * 128);
        a_xr[mt] = (uint32_t)((rowA & 7) << 4);
    }
    const uint32_t a_cb = (uint32_t)((lane >> 4) * 16);
    uint32_t b_rb[2], b_xr[2];
#pragma unroll
    for (int p = 0; p < 2; p++) {
        int nB = wn * 32 + p * 16 + ((lane >> 4) << 3) + (lane & 7);
        b_rb[p] = (uint32_t)(nB * 128);
        b_xr[p] = (uint32_t)((nB & 7) << 4);
    }
    const uint32_t b_cb = (uint32_t)(((lane >> 3) & 1) * 16);

    qkv_issue(sb, m0, n0, 0, tid);
    CP_COMMIT();

    for (int kc = 0; kc < 16; kc++) {
        if (kc < 15) {
            qkv_issue(sb + (uint32_t)(((kc + 1) & 1) * QSTG),
                      m0, n0, (kc + 1) * 64, tid);
            CP_COMMIT();
            CP_WAIT1();
        } else {
            CP_WAIT0();
        }
        __syncthreads();

        const uint32_t bufb = sb + (uint32_t)((kc & 1) * QSTG);
#pragma unroll
        for (int ks = 0; ks < 4; ks++) {
            const uint32_t acol = (a_cb + ks * 32);
            const uint32_t bcol = (b_cb + ks * 32);
            uint32_t ah[2][4], al[2][4];
#pragma unroll
            for (int mt = 0; mt < 2; mt++) {
                LDSM4(ah[mt][0], ah[mt][1], ah[mt][2], ah[mt][3],
                      bufb + a_rb[mt] + (acol ^ a_xr[mt]));
                LDSM4(al[mt][0], al[mt][1], al[mt][2], al[mt][3],
                      bufb + 16384 + a_rb[mt] + (acol ^ a_xr[mt]));
            }
            uint32_t bh[4][2];
#pragma unroll
            for (int p = 0; p < 2; p++) {
                uint32_t r0, r1, r2, r3;
                LDSM4(r0, r1, r2, r3, bufb + 32768 + b_rb[p] + (bcol ^ b_xr[p]));
                bh[2 * p][0] = r0; bh[2 * p][1] = r1;
                bh[2 * p + 1][0] = r2; bh[2 * p + 1][1] = r3;
            }
#pragma unroll
            for (int mt = 0; mt < 2; mt++)
#pragma unroll
                for (int nt = 0; nt < 4; nt++) {
                    MMA16816H(acc[mt][nt], ah[mt], bh[nt]);
                    MMA16816H(acc[mt][nt], al[mt], bh[nt]);
                }
        }
        __syncthreads();
    }

    // ---- epilogue: fp16 outputs. Q: hi+lo, K/V: hi only. ----
    const int sel = n0 >> 7;
    __half* oh = (sel == 0) ? g_q_hi : (sel == 1 ? g_k_hi : g_v_hi);
    const int colbase = n0 & 127;
    const int g = lane >> 2, tig = lane & 3;
#pragma unroll
    for (int mt = 0; mt < 2; mt++) {
        const int row0 = m0 + wm * 32 + mt * 16 + g;
#pragma unroll
        for (int nt = 0; nt < 4; nt++) {
            const int col = colbase + wn * 32 + nt * 8 + tig * 2;
#pragma unroll
            for (int h = 0; h < 2; h++) {
                const int row = row0 + h * 8;
                float a0 = acc[mt][nt][2 * h], a1 = acc[mt][nt][2 * h + 1];
                __half h0 = __float2half_rn(a0);
                __half h1 = __float2half_rn(a1);
                uint32_t hv = (uint32_t)__half_as_ushort(h0) |
                              ((uint32_t)__half_as_ushort(h1) << 16);
                *(uint32_t*)(oh + (size_t)row * H_ + col) = hv;
                if (sel == 0) {
                    *(uint32_t*)(g_q_lo + (size_t)row * H_ + col) =
                        pack_h2(a0 - __half2float(h0), a1 - __half2float(h1));
                }
            }
        }
    }
}

// ---------------------------------------------------------------------------
// Flash attention: S = (qh+ql) x k_hi (2-term); O += P_hi x V_hi (1-term).
// 256 threads, 4 row-groups x 2 col-halves, KV stage 32KB, 2 barriers/tile.
// ---------------------------------------------------------------------------
#define AQH 0
#define AQL 16384
#define AKV0 32768
#define KVBUF 32768
#define AEXM 98304
#define AEXS 98816
#define ATT_SMEM 99328

__device__ __forceinline__ void kv_issue256(uint32_t dstbase, size_t kbase, int tid)
{
#pragma unroll
    for (int i = 0; i < 4; i++) {
        int idx = i * 256 + tid;
        int r = idx >> 4, gq = idx & 15;
        uint32_t off = (uint32_t)(r * 256 + ((gq ^ (r & 7)) << 4));
        const size_t ge = kbase + (size_t)r * 128 + gq * 8;
        CP16(dstbase + off,         g_k_hi + ge);
        CP16(dstbase + 16384 + off, g_v_hi + ge);
    }
}

__global__ __launch_bounds__(256, 1) void attn_mma_kernel(float* __restrict__ out)
{
    extern __shared__ char smA[];
    const uint32_t sb = smem_u32(smA);
    float* mPart = (float*)(smA + AEXM);
    float* sPart = (float*)(smA + AEXS);

    const int tid  = threadIdx.x;
    const int lane = tid & 31, warp = tid >> 5;
    const int wr = warp & 3;
    const int wh = warp >> 2;
    const int b    = blockIdx.y;
    const int g4   = lane >> 2, tig = lane & 3;
    const int b3   = (lane >> 3) & 1;
    const int rk   = ((lane >> 4) << 3) + (lane & 7);
    const int xr7  = lane & 7;

    const int qrow = wr * 16 + (lane & 15);
    const uint32_t q_rb = (uint32_t)(qrow * 256);
    const uint32_t q_xr = (uint32_t)((qrow & 7));

    for (int pass = 0; pass < 2; pass++) {
        const int qt = pass ? (31 - (int)blockIdx.x) : (int)blockIdx.x;
        const size_t qbase = ((size_t)b * T_ + (size_t)qt * 64) * H_;
        const size_t batchbase = (size_t)b * T_ * H_;

        __syncthreads();
        kv_issue256(sb + AKV0, batchbase, tid);
        CP_COMMIT();

#pragma unroll
        for (int i = 0; i < 4; i++) {
            int idx = i * 256 + tid;
            int r = idx >> 4, gq = idx & 15;
            uint32_t off = (uint32_t)(r * 256 + ((gq ^ (r & 7)) << 4));
            *(uint4*)(smA + AQH + off) = *(const uint4*)(g_q_hi + qbase + r * 128 + gq * 8);
            *(uint4*)(smA + AQL + off) = *(const uint4*)(g_q_lo + qbase + r * 128 + gq * 8);
        }

        float oacc[16][4];
#pragma unroll
        for (int t = 0; t < 16; t++)
#pragma unroll
            for (int j = 0; j < 4; j++) oacc[t][j] = 0.f;
        float m0 = MASKV, m1 = MASKV, l0 = 0.f, l1 = 0.f;

        const int r0 = wr * 16 + g4, r1 = r0 + 8;

        for (int kt = 0; kt <= qt; kt++) {
            CP_WAIT0();
            __syncthreads();
            const uint32_t kvb = sb + AKV0 + (uint32_t)((kt & 1) * KVBUF);

            float sacc[4][4];
#pragma unroll
            for (int nt = 0; nt < 4; nt++)
#pragma unroll
                for (int j = 0; j < 4; j++) sacc[nt][j] = 0.f;

#pragma unroll
            for (int ks = 0; ks < 8; ks++) {
                uint32_t qh[4], ql[4];
                {
                    int gq = ks * 2 + (lane >> 4);
                    uint32_t off = q_rb + (uint32_t)((gq ^ q_xr) << 4);
                    LDSM4(qh[0], qh[1], qh[2], qh[3], sb + AQH + off);
                    LDSM4(ql[0], ql[1], ql[2], ql[3], sb + AQL + off);
                }
                const int gq = ks * 2 + b3;
                const uint32_t csw = (uint32_t)((gq ^ xr7) << 4);
#pragma unroll
                for (int p = 0; p < 2; p++) {
                    const uint32_t off =
                        (uint32_t)((wh * 32 + p * 16 + rk) * 256) + csw;
                    uint32_t h0, h1, h2, h3;
                    LDSM4(h0, h1, h2, h3, kvb + off);
                    uint32_t bh0[2] = {h0, h1}, bh1[2] = {h2, h3};
                    MMA16816H(sacc[2 * p],     qh, bh0);
                    MMA16816H(sacc[2 * p],     ql, bh0);
                    MMA16816H(sacc[2 * p + 1], qh, bh1);
                    MMA16816H(sacc[2 * p + 1], ql, bh1);
                }
            }

#pragma unroll
            for (int nt = 0; nt < 4; nt++)
#pragma unroll
                for (int j = 0; j < 4; j++) sacc[nt][j] *= SCALE2;
            if (kt == qt) {
#pragma unroll
                for (int nt = 0; nt < 4; nt++) {
                    const int c0 = wh * 32 + nt * 8 + tig * 2, c1 = c0 + 1;
                    if (c0 > r0) sacc[nt][0] = MASKV;
                    if (c1 > r0) sacc[nt][1] = MASKV;
                    if (c0 > r1) sacc[nt][2] = MASKV;
                    if (c1 > r1) sacc[nt][3] = MASKV;
                }
            }

            float rm0 = MASKV, rm1 = MASKV;
#pragma unroll
            for (int nt = 0; nt < 4; nt++) {
                rm0 = fmaxf(rm0, fmaxf(sacc[nt][0], sacc[nt][1]));
                rm1 = fmaxf(rm1, fmaxf(sacc[nt][2], sacc[nt][3]));
            }
            rm0 = fmaxf(rm0, __shfl_xor_sync(0xffffffffu, rm0, 1));
            rm0 = fmaxf(rm0, __shfl_xor_sync(0xffffffffu, rm0, 2));
            rm1 = fmaxf(rm1, __shfl_xor_sync(0xffffffffu, rm1, 1));
            rm1 = fmaxf(rm1, __shfl_xor_sync(0xffffffffu, rm1, 2));
            if (tig == 0) {
                mPart[wh * 64 + r0] = rm0;
                mPart[wh * 64 + r1] = rm1;
            }

            float rs0 = 0.f, rs1 = 0.f;
#pragma unroll
            for (int nt = 0; nt < 4; nt++) {
                float p0 = exp2f(sacc[nt][0] - rm0);
                float p1 = exp2f(sacc[nt][1] - rm0);
                float p2 = exp2f(sacc[nt][2] - rm1);
                float p3 = exp2f(sacc[nt][3] - rm1);
                sacc[nt][0] = p0; sacc[nt][1] = p1;
                sacc[nt][2] = p2; sacc[nt][3] = p3;
                rs0 += p0 + p1; rs1 += p2 + p3;
            }
            rs0 += __shfl_xor_sync(0xffffffffu, rs0, 1);
            rs0 += __shfl_xor_sync(0xffffffffu, rs0, 2);
            rs1 += __shfl_xor_sync(0xffffffffu, rs1, 1);
            rs1 += __shfl_xor_sync(0xffffffffu, rs1, 2);
            if (tig == 0) {
                sPart[wh * 64 + r0] = rs0;
                sPart[wh * 64 + r1] = rs1;
            }
            __syncthreads();

            if (kt < qt) {
                kv_issue256(sb + AKV0 + (uint32_t)(((kt + 1) & 1) * KVBUF),
                            batchbase + (size_t)(kt + 1) * 64 * H_, tid);
                CP_COMMIT();
            }

            const float rmA0 = mPart[r0], rmB0 = mPart[64 + r0];
            const float rmA1 = mPart[r1], rmB1 = mPart[64 + r1];
            const float mn0 = fmaxf(m0, fmaxf(rmA0, rmB0));
            const float mn1 = fmaxf(m1, fmaxf(rmA1, rmB1));
            const float corr0 = exp2f(m0 - mn0), corr1 = exp2f(m1 - mn1);
            l0 = l0 * corr0 + sPart[r0]      * exp2f(rmA0 - mn0)
                            + sPart[64 + r0] * exp2f(rmB0 - mn0);
            l1 = l1 * corr1 + sPart[r1]      * exp2f(rmA1 - mn1)
                            + sPart[64 + r1] * exp2f(rmB1 - mn1);
            m0 = mn0; m1 = mn1;
            const float fac0 = exp2f(rm0 - mn0);
            const float fac1 = exp2f(rm1 - mn1);

#pragma unroll
            for (int t = 0; t < 16; t++) {
                oacc[t][0] *= corr0; oacc[t][1] *= corr0;
                oacc[t][2] *= corr1; oacc[t][3] *= corr1;
            }

            // ---- P fp16 fragments (hi only, rescale folded) ----
            uint32_t ph[2][4];
#pragma unroll
            for (int c = 0; c < 2; c++) {
#pragma unroll
                for (int half = 0; half < 2; half++) {
                    const int nt = 2 * c + half;
                    ph[c][2 * half] =
                        pack_h2(sacc[nt][0] * fac0, sacc[nt][1] * fac0);
                    ph[c][2 * half + 1] =
                        pack_h2(sacc[nt][2] * fac1, sacc[nt][3] * fac1);
                }
            }

            // ---- O += P_hi x V_hi ----
#pragma unroll
            for (int c = 0; c < 2; c++) {
                const uint32_t roff = (uint32_t)(((wh * 2 + c) * 16 + rk) * 256);
#pragma unroll
                for (int jp = 0; jp < 8; jp++) {
                    const int gq = jp * 2 + b3;
                    const uint32_t off = roff + (uint32_t)((gq ^ xr7) << 4);
                    uint32_t t0, t1, t2, t3;
                    LDSM4T(t0, t1, t2, t3, kvb + 16384 + off);
                    uint32_t vh0[2] = {t0, t2}, vh1[2] = {t1, t3};
                    MMA16816H(oacc[2 * jp],     ph[c], vh0);
                    MMA16816H(oacc[2 * jp + 1], ph[c], vh1);
                }
            }
        }

        __syncthreads();
        if (wh == 1) {
            float* buf = (float*)(smA + AKV0 + wr * 8192);
#pragma unroll
            for (int t = 0; t < 16; t++) {
                const int col = t * 8 + tig * 2;
                *(float2*)&buf[g4 * 128 + col] =
                    make_float2(oacc[t][0], oacc[t][1]);
                *(float2*)&buf[(g4 + 8) * 128 + col] =
                    make_float2(oacc[t][2], oacc[t][3]);
            }
        }
        __syncthreads();
        if (wh == 0) {
            const float* buf = (const float*)(smA + AKV0 + wr * 8192);
            const float inv0 = 1.f / l0, inv1 = 1.f / l1;
#pragma unroll
            for (int t = 0; t < 16; t++) {
                const int col = t * 8 + tig * 2;
                float2 p0 = *(const float2*)&buf[g4 * 128 + col];
                float2 p1 = *(const float2*)&buf[(g4 + 8) * 128 + col];
                *(float2*)(out + qbase + (size_t)r0 * H_ + col) =
                    make_float2((oacc[t][0] + p0.x) * inv0,
                                (oacc[t][1] + p0.y) * inv0);
                *(float2*)(out + qbase + (size_t)r1 * H_ + col) =
                    make_float2((oacc[t][2] + p1.x) * inv1,
                                (oacc[t][3] + p1.y) * inv1);
            }
        }
    }
}

// ---------------------------------------------------------------------------
extern "C" void kernel_launch(void* const* d_in, const int* in_sizes, int n_in,
                              void* d_out, int out_size)
{
    const float* x  = (const float*)d_in[0];
    const float* Wq = (const float*)d_in[1];
    const float* Wk = (const float*)d_in[2];
    const float* Wv = (const float*)d_in[3];
    float* out = (float*)d_out;

    prep_kernel<<<4480, 256>>>(x, Wq, Wk, Wv);

    cudaFuncSetAttribute(qkv_mma_kernel,
                         cudaFuncAttributeMaxDynamicSharedMemorySize, QK_SMEM);
    qkv_mma_kernel<<<dim3(6, 128), 256, QK_SMEM>>>();

    cudaFuncSetAttribute(attn_mma_kernel,
                         cudaFuncAttributeMaxDynamicSharedMemorySize, ATT_SMEM);
    attn_mma_kernel<<<dim3(16, 8), 256, ATT_SMEM>>>(out);
}

// round 16
// speedup vs baseline: 1.8809x; 1.2768x over previous
#include <cuda_runtime.h>
#include <cuda_bf16.h>
#include <cuda_fp16.h>
#include <math.h>
#include <stdint.h>

#define B_ 8
#define T_ 2048
#define D_ 1024
#define H_ 128
#define SCALE2 0.12751763226289247f   // log2(e)/sqrt(128)
#define MASKV  (-1e30f)

__device__ __forceinline__ uint32_t smem_u32(const void* p) {
    uint32_t a;
    asm("{ .reg .u64 t; cvta.to.shared.u64 t, %1; cvt.u32.u64 %0, t; }"
        : "=r"(a) : "l"(p));
    return a;
}
__device__ __forceinline__ uint32_t pack_h2(float a, float b) {
    __half2 t = __floats2half2_rn(a, b);
    return *reinterpret_cast<uint32_t*>(&t);
}

#define CP16(dst, src) \
    asm volatile("cp.async.cg.shared.global [%0], [%1], 16;" \
                 :: "r"(dst), "l"(src) : "memory")
#define CP_COMMIT() asm volatile("cp.async.commit_group;" ::: "memory")
#define CP_WAIT0()  asm volatile("cp.async.wait_group 0;" ::: "memory")
#define CP_WAIT1()  asm volatile("cp.async.wait_group 1;" ::: "memory")

#define LDSM4(r0, r1, r2, r3, addr) \
    asm volatile("ldmatrix.sync.aligned.m8n8.x4.shared.b16 {%0,%1,%2,%3}, [%4];" \
                 : "=r"(r0), "=r"(r1), "=r"(r2), "=r"(r3) : "r"(addr))
#define LDSM4T(r0, r1, r2, r3, addr) \
    asm volatile("ldmatrix.sync.aligned.m8n8.x4.trans.shared.b16 {%0,%1,%2,%3}, [%4];" \
                 : "=r"(r0), "=r"(r1), "=r"(r2), "=r"(r3) : "r"(addr))

#define MMA16816H(d, a, b) \
    asm volatile("mma.sync.aligned.m16n8k16.row.col.f32.f16.f16.f32 " \
                 "{%0,%1,%2,%3},{%4,%5,%6,%7},{%8,%9},{%0,%1,%2,%3};" \
                 : "+f"((d)[0]), "+f"((d)[1]), "+f"((d)[2]), "+f"((d)[3]) \
                 : "r"((a)[0]), "r"((a)[1]), "r"((a)[2]), "r"((a)[3]), \
                   "r"((b)[0]), "r"((b)[1]))

// ---- device scratch (all fp16) ----
__device__ __half g_q_hi[(size_t)B_ * T_ * H_];
__device__ __half g_q_lo[(size_t)B_ * T_ * H_];
__device__ __half g_k_hi[(size_t)B_ * T_ * H_];
__device__ __half g_v_hi[(size_t)B_ * T_ * H_];
__device__ __half g_Wb_hi[384 * 1024];
__device__ __half g_x_hi[(size_t)B_ * T_ * D_];

// ---------------------------------------------------------------------------
// Fused prep, MLP=4: X -> fp16 hi only; Wcat -> fp16 hi only.
// ---------------------------------------------------------------------------
__global__ __launch_bounds__(256) void prep_kernel(
    const float* __restrict__ x,
    const float* __restrict__ Wq,
    const float* __restrict__ Wk,
    const float* __restrict__ Wv)
{
    if (blockIdx.x < 4096) {
        const size_t base = (size_t)blockIdx.x * 1024 + threadIdx.x;
        float4 f[4];
#pragma unroll
        for (int k = 0; k < 4; k++) f[k] = ((const float4*)x)[base + k * 256];
#pragma unroll
        for (int k = 0; k < 4; k++) {
            uint2 hv;
            hv.x = pack_h2(f[k].x, f[k].y);
            hv.y = pack_h2(f[k].z, f[k].w);
            ((uint2*)g_x_hi)[base + k * 256] = hv;
        }
    } else {
        const int n = blockIdx.x - 4096;
        const float* W = (n < 128) ? Wq : (n < 256 ? Wk : Wv);
        const int h = n & 127;
        for (int k = threadIdx.x; k < 1024; k += 256) {
            g_Wb_hi[(size_t)n * 1024 + k] = __float2half_rn(W[(size_t)k * H_ + h]);
        }
    }
}

// ---------------------------------------------------------------------------
// QKV GEMM: single-term fp16 (x_h x w_h). CTA 128x64, 256 thr, warps 4x2,
// 4 CTAs/SM. Stage: AH 0 (16K) | BH 16K (8K) = 24KB. Two stages = 48KB.
// ---------------------------------------------------------------------------
#define QSTG 24576
#define QK_SMEM (2 * QSTG)

__device__ __forceinline__ void qkv_issue(uint32_t dstbase, int m0, int n0,
                                          int k0, int tid)
{
#pragma unroll
    for (int i = 0; i < 4; i++) {
        int idx = i * 256 + tid;
        int r = idx >> 3, g = idx & 7;
        uint32_t off = (uint32_t)(r * 128 + ((g ^ (r & 7)) << 4));
        const size_t ax = (size_t)(m0 + r) * D_ + k0 + g * 8;
        CP16(dstbase + off, g_x_hi + ax);
    }
#pragma unroll
    for (int i = 0; i < 2; i++) {
        int idx = i * 256 + tid;
        int r = idx >> 3, g = idx & 7;
        uint32_t off = (uint32_t)(r * 128 + ((g ^ (r & 7)) << 4));
        const size_t bx = (size_t)(n0 + r) * D_ + k0 + g * 8;
        CP16(dstbase + 16384 + off, g_Wb_hi + bx);
    }
}

__global__ __launch_bounds__(256, 4) void qkv_mma_kernel()
{
    extern __shared__ char smq[];
    const uint32_t sb = smem_u32(smq);
    const int tid  = threadIdx.x;
    const int lane = tid & 31, warp = tid >> 5;
    const int wm = warp >> 1, wn = warp & 1;
    const int m0 = blockIdx.y * 128;
    const int n0 = blockIdx.x * 64;

    float acc[2][4][4];
#pragma unroll
    for (int mt = 0; mt < 2; mt++)
#pragma unroll
        for (int nt = 0; nt < 4; nt++)
#pragma unroll
            for (int j = 0; j < 4; j++) acc[mt][nt][j] = 0.f;

    uint32_t a_rb[2], a_xr[2];
#pragma unroll
    for (int mt = 0; mt < 2; mt++) {
        int rowA = wm * 32 + mt * 16 + (lane & 15);
        a_rb[mt] = (uint32_t)(rowA * 128);
        a_xr[mt] = (uint32_t)((rowA & 7) << 4);
    }
    const uint32_t a_cb = (uint32_t)((lane >> 4) * 16);
    uint32_t b_rb[2], b_xr[2];
#pragma unroll
    for (int p = 0; p < 2; p++) {
        int nB = wn * 32 + p * 16 + ((lane >> 4) << 3) + (lane & 7);
        b_rb[p] = (uint32_t)(nB * 128);
        b_xr[p] = (uint32_t)((nB & 7) << 4);
    }
    const uint32_t b_cb = (uint32_t)(((lane >> 3) & 1) * 16);

    qkv_issue(sb, m0, n0, 0, tid);
    CP_COMMIT();

    for (int kc = 0; kc < 16; kc++) {
        if (kc < 15) {
            qkv_issue(sb + (uint32_t)(((kc + 1) & 1) * QSTG),
                      m0, n0, (kc + 1) * 64, tid);
            CP_COMMIT();
            CP_WAIT1();
        } else {
            CP_WAIT0();
        }
        __syncthreads();

        const uint32_t bufb = sb + (uint32_t)((kc & 1) * QSTG);
#pragma unroll
        for (int ks = 0; ks < 4; ks++) {
            const uint32_t acol = (a_cb + ks * 32);
            const uint32_t bcol = (b_cb + ks * 32);
            uint32_t ah[2][4];
#pragma unroll
            for (int mt = 0; mt < 2; mt++) {
                LDSM4(ah[mt][0], ah[mt][1], ah[mt][2], ah[mt][3],
                      bufb + a_rb[mt] + (acol ^ a_xr[mt]));
            }
            uint32_t bh[4][2];
#pragma unroll
            for (int p = 0; p < 2; p++) {
                uint32_t r0, r1, r2, r3;
                LDSM4(r0, r1, r2, r3, bufb + 16384 + b_rb[p] + (bcol ^ b_xr[p]));
                bh[2 * p][0] = r0; bh[2 * p][1] = r1;
                bh[2 * p + 1][0] = r2; bh[2 * p + 1][1] = r3;
            }
#pragma unroll
            for (int mt = 0; mt < 2; mt++)
#pragma unroll
                for (int nt = 0; nt < 4; nt++) {
                    MMA16816H(acc[mt][nt], ah[mt], bh[nt]);
                }
        }
        __syncthreads();
    }

    // ---- epilogue: fp16 outputs. Q: hi+lo, K/V: hi only. ----
    const int sel = n0 >> 7;
    __half* oh = (sel == 0) ? g_q_hi : (sel == 1 ? g_k_hi : g_v_hi);
    const int colbase = n0 & 127;
    const int g = lane >> 2, tig = lane & 3;
#pragma unroll
    for (int mt = 0; mt < 2; mt++) {
        const int row0 = m0 + wm * 32 + mt * 16 + g;
#pragma unroll
        for (int nt = 0; nt < 4; nt++) {
            const int col = colbase + wn * 32 + nt * 8 + tig * 2;
#pragma unroll
            for (int h = 0; h < 2; h++) {
                const int row = row0 + h * 8;
                float a0 = acc[mt][nt][2 * h], a1 = acc[mt][nt][2 * h + 1];
                __half h0 = __float2half_rn(a0);
                __half h1 = __float2half_rn(a1);
                uint32_t hv = (uint32_t)__half_as_ushort(h0) |
                              ((uint32_t)__half_as_ushort(h1) << 16);
                *(uint32_t*)(oh + (size_t)row * H_ + col) = hv;
                if (sel == 0) {
                    *(uint32_t*)(g_q_lo + (size_t)row * H_ + col) =
                        pack_h2(a0 - __half2float(h0), a1 - __half2float(h1));
                }
            }
        }
    }
}

// ---------------------------------------------------------------------------
// Flash attention (R15, unchanged): S = (qh+ql) x k_hi; O += P_hi x V_hi.
// 256 threads, 4 row-groups x 2 col-halves, KV stage 32KB, 2 barriers/tile.
// ---------------------------------------------------------------------------
#define AQH 0
#define AQL 16384
#define AKV0 32768
#define KVBUF 32768
#define AEXM 98304
#define AEXS 98816
#define ATT_SMEM 99328

__device__ __forceinline__ void kv_issue256(uint32_t dstbase, size_t kbase, int tid)
{
#pragma unroll
    for (int i = 0; i < 4; i++) {
        int idx = i * 256 + tid;
        int r = idx >> 4, gq = idx & 15;
        uint32_t off = (uint32_t)(r * 256 + ((gq ^ (r & 7)) << 4));
        const size_t ge = kbase + (size_t)r * 128 + gq * 8;
        CP16(dstbase + off,         g_k_hi + ge);
        CP16(dstbase + 16384 + off, g_v_hi + ge);
    }
}

__global__ __launch_bounds__(256, 1) void attn_mma_kernel(float* __restrict__ out)
{
    extern __shared__ char smA[];
    const uint32_t sb = smem_u32(smA);
    float* mPart = (float*)(smA + AEXM);
    float* sPart = (float*)(smA + AEXS);

    const int tid  = threadIdx.x;
    const int lane = tid & 31, warp = tid >> 5;
    const int wr = warp & 3;
    const int wh = warp >> 2;
    const int b    = blockIdx.y;
    const int g4   = lane >> 2, tig = lane & 3;
    const int b3   = (lane >> 3) & 1;
    const int rk   = ((lane >> 4) << 3) + (lane & 7);
    const int xr7  = lane & 7;

    const int qrow = wr * 16 + (lane & 15);
    const uint32_t q_rb = (uint32_t)(qrow * 256);
    const uint32_t q_xr = (uint32_t)((qrow & 7));

    for (int pass = 0; pass < 2; pass++) {
        const int qt = pass ? (31 - (int)blockIdx.x) : (int)blockIdx.x;
        const size_t qbase = ((size_t)b * T_ + (size_t)qt * 64) * H_;
        const size_t batchbase = (size_t)b * T_ * H_;

        __syncthreads();
        kv_issue256(sb + AKV0, batchbase, tid);
        CP_COMMIT();

#pragma unroll
        for (int i = 0; i < 4; i++) {
            int idx = i * 256 + tid;
            int r = idx >> 4, gq = idx & 15;
            uint32_t off = (uint32_t)(r * 256 + ((gq ^ (r & 7)) << 4));
            *(uint4*)(smA + AQH + off) = *(const uint4*)(g_q_hi + qbase + r * 128 + gq * 8);
            *(uint4*)(smA + AQL + off) = *(const uint4*)(g_q_lo + qbase + r * 128 + gq * 8);
        }

        float oacc[16][4];
#pragma unroll
        for (int t = 0; t < 16; t++)
#pragma unroll
            for (int j = 0; j < 4; j++) oacc[t][j] = 0.f;
        float m0 = MASKV, m1 = MASKV, l0 = 0.f, l1 = 0.f;

        const int r0 = wr * 16 + g4, r1 = r0 + 8;

        for (int kt = 0; kt <= qt; kt++) {
            CP_WAIT0();
            __syncthreads();
            const uint32_t kvb = sb + AKV0 + (uint32_t)((kt & 1) * KVBUF);

            float sacc[4][4];
#pragma unroll
            for (int nt = 0; nt < 4; nt++)
#pragma unroll
                for (int j = 0; j < 4; j++) sacc[nt][j] = 0.f;

#pragma unroll
            for (int ks = 0; ks < 8; ks++) {
                uint32_t qh[4], ql[4];
                {
                    int gq = ks * 2 + (lane >> 4);
                    uint32_t off = q_rb + (uint32_t)((gq ^ q_xr) << 4);
                    LDSM4(qh[0], qh[1], qh[2], qh[3], sb + AQH + off);
                    LDSM4(ql[0], ql[1], ql[2], ql[3], sb + AQL + off);
                }
                const int gq = ks * 2 + b3;
                const uint32_t csw = (uint32_t)((gq ^ xr7) << 4);
#pragma unroll
                for (int p = 0; p < 2; p++) {
                    const uint32_t off =
                        (uint32_t)((wh * 32 + p * 16 + rk) * 256) + csw;
                    uint32_t h0, h1, h2, h3;
                    LDSM4(h0, h1, h2, h3, kvb + off);
                    uint32_t bh0[2] = {h0, h1}, bh1[2] = {h2, h3};
                    MMA16816H(sacc[2 * p],     qh, bh0);
                    MMA16816H(sacc[2 * p],     ql, bh0);
                    MMA16816H(sacc[2 * p + 1], qh, bh1);
                    MMA16816H(sacc[2 * p + 1], ql, bh1);
                }
            }

#pragma unroll
            for (int nt = 0; nt < 4; nt++)
#pragma unroll
                for (int j = 0; j < 4; j++) sacc[nt][j] *= SCALE2;
            if (kt == qt) {
#pragma unroll
                for (int nt = 0; nt < 4; nt++) {
                    const int c0 = wh * 32 + nt * 8 + tig * 2, c1 = c0 + 1;
                    if (c0 > r0) sacc[nt][0] = MASKV;
                    if (c1 > r0) sacc[nt][1] = MASKV;
                    if (c0 > r1) sacc[nt][2] = MASKV;
                    if (c1 > r1) sacc[nt][3] = MASKV;
                }
            }

            float rm0 = MASKV, rm1 = MASKV;
#pragma unroll
            for (int nt = 0; nt < 4; nt++) {
                rm0 = fmaxf(rm0, fmaxf(sacc[nt][0], sacc[nt][1]));
                rm1 = fmaxf(rm1, fmaxf(sacc[nt][2], sacc[nt][3]));
            }
            rm0 = fmaxf(rm0, __shfl_xor_sync(0xffffffffu, rm0, 1));
            rm0 = fmaxf(rm0, __shfl_xor_sync(0xffffffffu, rm0, 2));
            rm1 = fmaxf(rm1, __shfl_xor_sync(0xffffffffu, rm1, 1));
            rm1 = fmaxf(rm1, __shfl_xor_sync(0xffffffffu, rm1, 2));
            if (tig == 0) {
                mPart[wh * 64 + r0] = rm0;
                mPart[wh * 64 + r1] = rm1;
            }

            float rs0 = 0.f, rs1 = 0.f;
#pragma unroll
            for (int nt = 0; nt < 4; nt++) {
                float p0 = exp2f(sacc[nt][0] - rm0);
                float p1 = exp2f(sacc[nt][1] - rm0);
                float p2 = exp2f(sacc[nt][2] - rm1);
                float p3 = exp2f(sacc[nt][3] - rm1);
                sacc[nt][0] = p0; sacc[nt][1] = p1;
                sacc[nt][2] = p2; sacc[nt][3] = p3;
                rs0 += p0 + p1; rs1 += p2 + p3;
            }
            rs0 += __shfl_xor_sync(0xffffffffu, rs0, 1);
            rs0 += __shfl_xor_sync(0xffffffffu, rs0, 2);
            rs1 += __shfl_xor_sync(0xffffffffu, rs1, 1);
            rs1 += __shfl_xor_sync(0xffffffffu, rs1, 2);
            if (tig == 0) {
                sPart[wh * 64 + r0] = rs0;
                sPart[wh * 64 + r1] = rs1;
            }
            __syncthreads();

            if (kt < qt) {
                kv_issue256(sb + AKV0 + (uint32_t)(((kt + 1) & 1) * KVBUF),
                            batchbase + (size_t)(kt + 1) * 64 * H_, tid);
                CP_COMMIT();
            }

            const float rmA0 = mPart[r0], rmB0 = mPart[64 + r0];
            const float rmA1 = mPart[r1], rmB1 = mPart[64 + r1];
            const float mn0 = fmaxf(m0, fmaxf(rmA0, rmB0));
            const float mn1 = fmaxf(m1, fmaxf(rmA1, rmB1));
            const float corr0 = exp2f(m0 - mn0), corr1 = exp2f(m1 - mn1);
            l0 = l0 * corr0 + sPart[r0]      * exp2f(rmA0 - mn0)
                            + sPart[64 + r0] * exp2f(rmB0 - mn0);
            l1 = l1 * corr1 + sPart[r1]      * exp2f(rmA1 - mn1)
                            + sPart[64 + r1] * exp2f(rmB1 - mn1);
            m0 = mn0; m1 = mn1;
            const float fac0 = exp2f(rm0 - mn0);
            const float fac1 = exp2f(rm1 - mn1);

#pragma unroll
            for (int t = 0; t < 16; t++) {
                oacc[t][0] *= corr0; oacc[t][1] *= corr0;
                oacc[t][2] *= corr1; oacc[t][3] *= corr1;
            }

            uint32_t ph[2][4];
#pragma unroll
            for (int c = 0; c < 2; c++) {
#pragma unroll
                for (int half = 0; half < 2; half++) {
                    const int nt = 2 * c + half;
                    ph[c][2 * half] =
                        pack_h2(sacc[nt][0] * fac0, sacc[nt][1] * fac0);
                    ph[c][2 * half + 1] =
                        pack_h2(sacc[nt][2] * fac1, sacc[nt][3] * fac1);
                }
            }

#pragma unroll
            for (int c = 0; c < 2; c++) {
                const uint32_t roff = (uint32_t)(((wh * 2 + c) * 16 + rk) * 256);
#pragma unroll
                for (int jp = 0; jp < 8; jp++) {
                    const int gq = jp * 2 + b3;
                    const uint32_t off = roff + (uint32_t)((gq ^ xr7) << 4);
                    uint32_t t0, t1, t2, t3;
                    LDSM4T(t0, t1, t2, t3, kvb + 16384 + off);
                    uint32_t vh0[2] = {t0, t2}, vh1[2] = {t1, t3};
                    MMA16816H(oacc[2 * jp],     ph[c], vh0);
                    MMA16816H(oacc[2 * jp + 1], ph[c], vh1);
                }
            }
        }

        __syncthreads();
        if (wh == 1) {
            float* buf = (float*)(smA + AKV0 + wr * 8192);
#pragma unroll
            for (int t = 0; t < 16; t++) {
                const int col = t * 8 + tig * 2;
                *(float2*)&buf[g4 * 128 + col] =
                    make_float2(oacc[t][0], oacc[t][1]);
                *(float2*)&buf[(g4 + 8) * 128 + col] =
                    make_float2(oacc[t][2], oacc[t][3]);
            }
        }
        __syncthreads();
        if (wh == 0) {
            const float* buf = (const float*)(smA + AKV0 + wr * 8192);
            const float inv0 = 1.f / l0, inv1 = 1.f / l1;
#pragma unroll
            for (int t = 0; t < 16; t++) {
                const int col = t * 8 + tig * 2;
                float2 p0 = *(const float2*)&buf[g4 * 128 + col];
                float2 p1 = *(const float2*)&buf[(g4 + 8) * 128 + col];
                *(float2*)(out + qbase + (size_t)r0 * H_ + col) =
                    make_float2((oacc[t][0] + p0.x) * inv0,
                                (oacc[t][1] + p0.y) * inv0);
                *(float2*)(out + qbase + (size_t)r1 * H_ + col) =
                    make_float2((oacc[t][2] + p1.x) * inv1,
                                (oacc[t][3] + p1.y) * inv1);
            }
        }
    }
}

// ---------------------------------------------------------------------------
extern "C" void kernel_launch(void* const* d_in, const int* in_sizes, int n_in,
                              void* d_out, int out_size)
{
    const float* x  = (const float*)d_in[0];
    const float* Wq = (const float*)d_in[1];
    const float* Wk = (const float*)d_in[2];
    const float* Wv = (const float*)d_in[3];
    float* out = (float*)d_out;

    prep_kernel<<<4480, 256>>>(x, Wq, Wk, Wv);

    cudaFuncSetAttribute(qkv_mma_kernel,
                         cudaFuncAttributeMaxDynamicSharedMemorySize, QK_SMEM);
    qkv_mma_kernel<<<dim3(6, 128), 256, QK_SMEM>>>();

    cudaFuncSetAttribute(attn_mma_kernel,
                         cudaFuncAttributeMaxDynamicSharedMemorySize, ATT_SMEM);
    attn_mma_kernel<<<dim3(16, 8), 256, ATT_SMEM>>>(out);
}

// round 17
// speedup vs baseline: 1.9830x; 1.0543x over previous
#include <cuda_runtime.h>
#include <cuda_bf16.h>
#include <cuda_fp16.h>
#include <math.h>
#include <stdint.h>

#define B_ 8
#define T_ 2048
#define D_ 1024
#define H_ 128
#define SCALE2 0.12751763226289247f   // log2(e)/sqrt(128)
#define MASKV  (-1e30f)

__device__ __forceinline__ uint32_t smem_u32(const void* p) {
    uint32_t a;
    asm("{ .reg .u64 t; cvta.to.shared.u64 t, %1; cvt.u32.u64 %0, t; }"
        : "=r"(a) : "l"(p));
    return a;
}
__device__ __forceinline__ uint32_t pack_h2(float a, float b) {
    __half2 t = __floats2half2_rn(a, b);
    return *reinterpret_cast<uint32_t*>(&t);
}

#define CP16(dst, src) \
    asm volatile("cp.async.cg.shared.global [%0], [%1], 16;" \
                 :: "r"(dst), "l"(src) : "memory")
#define CP_COMMIT() asm volatile("cp.async.commit_group;" ::: "memory")
#define CP_WAIT0()  asm volatile("cp.async.wait_group 0;" ::: "memory")
#define CP_WAIT1()  asm volatile("cp.async.wait_group 1;" ::: "memory")

#define LDSM4(r0, r1, r2, r3, addr) \
    asm volatile("ldmatrix.sync.aligned.m8n8.x4.shared.b16 {%0,%1,%2,%3}, [%4];" \
                 : "=r"(r0), "=r"(r1), "=r"(r2), "=r"(r3) : "r"(addr))
#define LDSM4T(r0, r1, r2, r3, addr) \
    asm volatile("ldmatrix.sync.aligned.m8n8.x4.trans.shared.b16 {%0,%1,%2,%3}, [%4];" \
                 : "=r"(r0), "=r"(r1), "=r"(r2), "=r"(r3) : "r"(addr))

#define MMA16816H(d, a, b) \
    asm volatile("mma.sync.aligned.m16n8k16.row.col.f32.f16.f16.f32 " \
                 "{%0,%1,%2,%3},{%4,%5,%6,%7},{%8,%9},{%0,%1,%2,%3};" \
                 : "+f"((d)[0]), "+f"((d)[1]), "+f"((d)[2]), "+f"((d)[3]) \
                 : "r"((a)[0]), "r"((a)[1]), "r"((a)[2]), "r"((a)[3]), \
                   "r"((b)[0]), "r"((b)[1]))

// ---- device scratch (all fp16) ----
__device__ __half g_q_hi[(size_t)B_ * T_ * H_];
__device__ __half g_k_hi[(size_t)B_ * T_ * H_];
__device__ __half g_v_hi[(size_t)B_ * T_ * H_];
__device__ __half g_Wb_hi[384 * 1024];
__device__ __half g_x_hi[(size_t)B_ * T_ * D_];

// ---------------------------------------------------------------------------
// Fused prep, MLP=4: X -> fp16; Wcat -> fp16.
// ---------------------------------------------------------------------------
__global__ __launch_bounds__(256) void prep_kernel(
    const float* __restrict__ x,
    const float* __restrict__ Wq,
    const float* __restrict__ Wk,
    const float* __restrict__ Wv)
{
    if (blockIdx.x < 4096) {
        const size_t base = (size_t)blockIdx.x * 1024 + threadIdx.x;
        float4 f[4];
#pragma unroll
        for (int k = 0; k < 4; k++) f[k] = ((const float4*)x)[base + k * 256];
#pragma unroll
        for (int k = 0; k < 4; k++) {
            uint2 hv;
            hv.x = pack_h2(f[k].x, f[k].y);
            hv.y = pack_h2(f[k].z, f[k].w);
            ((uint2*)g_x_hi)[base + k * 256] = hv;
        }
    } else {
        const int n = blockIdx.x - 4096;
        const float* W = (n < 128) ? Wq : (n < 256 ? Wk : Wv);
        const int h = n & 127;
        for (int k = threadIdx.x; k < 1024; k += 256) {
            g_Wb_hi[(size_t)n * 1024 + k] = __float2half_rn(W[(size_t)k * H_ + h]);
        }
    }
}

// ---------------------------------------------------------------------------
// QKV GEMM: single-term fp16 (x_h x w_h). CTA 128x64, 256 thr, warps 4x2,
// 4 CTAs/SM. Stage: AH 0 (16K) | BH 16K (8K) = 24KB. Two stages = 48KB.
// ---------------------------------------------------------------------------
#define QSTG 24576
#define QK_SMEM (2 * QSTG)

__device__ __forceinline__ void qkv_issue(uint32_t dstbase, int m0, int n0,
                                          int k0, int tid)
{
#pragma unroll
    for (int i = 0; i < 4; i++) {
        int idx = i * 256 + tid;
        int r = idx >> 3, g = idx & 7;
        uint32_t off = (uint32_t)(r * 128 + ((g ^ (r & 7)) << 4));
        const size_t ax = (size_t)(m0 + r) * D_ + k0 + g * 8;
        CP16(dstbase + off, g_x_hi + ax);
    }
#pragma unroll
    for (int i = 0; i < 2; i++) {
        int idx = i * 256 + tid;
        int r = idx >> 3, g = idx & 7;
        uint32_t off = (uint32_t)(r * 128 + ((g ^ (r & 7)) << 4));
        const size_t bx = (size_t)(n0 + r) * D_ + k0 + g * 8;
        CP16(dstbase + 16384 + off, g_Wb_hi + bx);
    }
}

__global__ __launch_bounds__(256, 4) void qkv_mma_kernel()
{
    extern __shared__ char smq[];
    const uint32_t sb = smem_u32(smq);
    const int tid  = threadIdx.x;
    const int lane = tid & 31, warp = tid >> 5;
    const int wm = warp >> 1, wn = warp & 1;
    const int m0 = blockIdx.y * 128;
    const int n0 = blockIdx.x * 64;

    float acc[2][4][4];
#pragma unroll
    for (int mt = 0; mt < 2; mt++)
#pragma unroll
        for (int nt = 0; nt < 4; nt++)
#pragma unroll
            for (int j = 0; j < 4; j++) acc[mt][nt][j] = 0.f;

    uint32_t a_rb[2], a_xr[2];
#pragma unroll
    for (int mt = 0; mt < 2; mt++) {
        int rowA = wm * 32 + mt * 16 + (lane & 15);
        a_rb[mt] = (uint32_t)(rowA * 128);
        a_xr[mt] = (uint32_t)((rowA & 7) << 4);
    }
    const uint32_t a_cb = (uint32_t)((lane >> 4) * 16);
    uint32_t b_rb[2], b_xr[2];
#pragma unroll
    for (int p = 0; p < 2; p++) {
        int nB = wn * 32 + p * 16 + ((lane >> 4) << 3) + (lane & 7);
        b_rb[p] = (uint32_t)(nB * 128);
        b_xr[p] = (uint32_t)((nB & 7) << 4);
    }
    const uint32_t b_cb = (uint32_t)(((lane >> 3) & 1) * 16);

    qkv_issue(sb, m0, n0, 0, tid);
    CP_COMMIT();

    for (int kc = 0; kc < 16; kc++) {
        if (kc < 15) {
            qkv_issue(sb + (uint32_t)(((kc + 1) & 1) * QSTG),
                      m0, n0, (kc + 1) * 64, tid);
            CP_COMMIT();
            CP_WAIT1();
        } else {
            CP_WAIT0();
        }
        __syncthreads();

        const uint32_t bufb = sb + (uint32_t)((kc & 1) * QSTG);
#pragma unroll
        for (int ks = 0; ks < 4; ks++) {
            const uint32_t acol = (a_cb + ks * 32);
            const uint32_t bcol = (b_cb + ks * 32);
            uint32_t ah[2][4];
#pragma unroll
            for (int mt = 0; mt < 2; mt++) {
                LDSM4(ah[mt][0], ah[mt][1], ah[mt][2], ah[mt][3],
                      bufb + a_rb[mt] + (acol ^ a_xr[mt]));
            }
            uint32_t bh[4][2];
#pragma unroll
            for (int p = 0; p < 2; p++) {
                uint32_t r0, r1, r2, r3;
                LDSM4(r0, r1, r2, r3, bufb + 16384 + b_rb[p] + (bcol ^ b_xr[p]));
                bh[2 * p][0] = r0; bh[2 * p][1] = r1;
                bh[2 * p + 1][0] = r2; bh[2 * p + 1][1] = r3;
            }
#pragma unroll
            for (int mt = 0; mt < 2; mt++)
#pragma unroll
                for (int nt = 0; nt < 4; nt++) {
                    MMA16816H(acc[mt][nt], ah[mt], bh[nt]);
                }
        }
        __syncthreads();
    }

    // ---- epilogue: fp16 outputs ----
    const int sel = n0 >> 7;
    __half* oh = (sel == 0) ? g_q_hi : (sel == 1 ? g_k_hi : g_v_hi);
    const int colbase = n0 & 127;
    const int g = lane >> 2, tig = lane & 3;
#pragma unroll
    for (int mt = 0; mt < 2; mt++) {
        const int row0 = m0 + wm * 32 + mt * 16 + g;
#pragma unroll
        for (int nt = 0; nt < 4; nt++) {
            const int col = colbase + wn * 32 + nt * 8 + tig * 2;
#pragma unroll
            for (int h = 0; h < 2; h++) {
                const int row = row0 + h * 8;
                *(uint32_t*)(oh + (size_t)row * H_ + col) =
                    pack_h2(acc[mt][nt][2 * h], acc[mt][nt][2 * h + 1]);
            }
        }
    }
}

// ---------------------------------------------------------------------------
// Flash attention: S = q_hi x k_hi (1-term); O += P_hi x V_hi (1-term).
// 256 threads, 4 row-groups x 2 col-halves, KV stage 32KB, 2 barriers/tile.
// smem: QH 0 (16K) | KV stage0 16K..48K | stage1 48K..80K | mPart/sPart 80K.
// ---------------------------------------------------------------------------
#define AQH 0
#define AKV0 16384
#define KVBUF 32768
#define AEXM 81920
#define AEXS 82432
#define ATT_SMEM 82944

__device__ __forceinline__ void kv_issue256(uint32_t dstbase, size_t kbase, int tid)
{
#pragma unroll
    for (int i = 0; i < 4; i++) {
        int idx = i * 256 + tid;
        int r = idx >> 4, gq = idx & 15;
        uint32_t off = (uint32_t)(r * 256 + ((gq ^ (r & 7)) << 4));
        const size_t ge = kbase + (size_t)r * 128 + gq * 8;
        CP16(dstbase + off,         g_k_hi + ge);
        CP16(dstbase + 16384 + off, g_v_hi + ge);
    }
}

__global__ __launch_bounds__(256, 1) void attn_mma_kernel(float* __restrict__ out)
{
    extern __shared__ char smA[];
    const uint32_t sb = smem_u32(smA);
    float* mPart = (float*)(smA + AEXM);
    float* sPart = (float*)(smA + AEXS);

    const int tid  = threadIdx.x;
    const int lane = tid & 31, warp = tid >> 5;
    const int wr = warp & 3;
    const int wh = warp >> 2;
    const int b    = blockIdx.y;
    const int g4   = lane >> 2, tig = lane & 3;
    const int b3   = (lane >> 3) & 1;
    const int rk   = ((lane >> 4) << 3) + (lane & 7);
    const int xr7  = lane & 7;

    const int qrow = wr * 16 + (lane & 15);
    const uint32_t q_rb = (uint32_t)(qrow * 256);
    const uint32_t q_xr = (uint32_t)((qrow & 7));

    for (int pass = 0; pass < 2; pass++) {
        const int qt = pass ? (31 - (int)blockIdx.x) : (int)blockIdx.x;
        const size_t qbase = ((size_t)b * T_ + (size_t)qt * 64) * H_;
        const size_t batchbase = (size_t)b * T_ * H_;

        __syncthreads();
        kv_issue256(sb + AKV0, batchbase, tid);
        CP_COMMIT();

        // stage Q (hi only): 64 rows x 16 granules
#pragma unroll
        for (int i = 0; i < 4; i++) {
            int idx = i * 256 + tid;
            int r = idx >> 4, gq = idx & 15;
            uint32_t off = (uint32_t)(r * 256 + ((gq ^ (r & 7)) << 4));
            *(uint4*)(smA + AQH + off) = *(const uint4*)(g_q_hi + qbase + r * 128 + gq * 8);
        }

        float oacc[16][4];
#pragma unroll
        for (int t = 0; t < 16; t++)
#pragma unroll
            for (int j = 0; j < 4; j++) oacc[t][j] = 0.f;
        float m0 = MASKV, m1 = MASKV, l0 = 0.f, l1 = 0.f;

        const int r0 = wr * 16 + g4, r1 = r0 + 8;

        for (int kt = 0; kt <= qt; kt++) {
            CP_WAIT0();
            __syncthreads();
            const uint32_t kvb = sb + AKV0 + (uint32_t)((kt & 1) * KVBUF);

            // ---- S = q_hi K^T ----
            float sacc[4][4];
#pragma unroll
            for (int nt = 0; nt < 4; nt++)
#pragma unroll
                for (int j = 0; j < 4; j++) sacc[nt][j] = 0.f;

#pragma unroll
            for (int ks = 0; ks < 8; ks++) {
                uint32_t qh[4];
                {
                    int gq = ks * 2 + (lane >> 4);
                    uint32_t off = q_rb + (uint32_t)((gq ^ q_xr) << 4);
                    LDSM4(qh[0], qh[1], qh[2], qh[3], sb + AQH + off);
                }
                const int gq = ks * 2 + b3;
                const uint32_t csw = (uint32_t)((gq ^ xr7) << 4);
#pragma unroll
                for (int p = 0; p < 2; p++) {
                    const uint32_t off =
                        (uint32_t)((wh * 32 + p * 16 + rk) * 256) + csw;
                    uint32_t h0, h1, h2, h3;
                    LDSM4(h0, h1, h2, h3, kvb + off);
                    uint32_t bh0[2] = {h0, h1}, bh1[2] = {h2, h3};
                    MMA16816H(sacc[2 * p],     qh, bh0);
                    MMA16816H(sacc[2 * p + 1], qh, bh1);
                }
            }

#pragma unroll
            for (int nt = 0; nt < 4; nt++)
#pragma unroll
                for (int j = 0; j < 4; j++) sacc[nt][j] *= SCALE2;
            if (kt == qt) {
#pragma unroll
                for (int nt = 0; nt < 4; nt++) {
                    const int c0 = wh * 32 + nt * 8 + tig * 2, c1 = c0 + 1;
                    if (c0 > r0) sacc[nt][0] = MASKV;
                    if (c1 > r0) sacc[nt][1] = MASKV;
                    if (c0 > r1) sacc[nt][2] = MASKV;
                    if (c1 > r1) sacc[nt][3] = MASKV;
                }
            }

            float rm0 = MASKV, rm1 = MASKV;
#pragma unroll
            for (int nt = 0; nt < 4; nt++) {
                rm0 = fmaxf(rm0, fmaxf(sacc[nt][0], sacc[nt][1]));
                rm1 = fmaxf(rm1, fmaxf(sacc[nt][2], sacc[nt][3]));
            }
            rm0 = fmaxf(rm0, __shfl_xor_sync(0xffffffffu, rm0, 1));
            rm0 = fmaxf(rm0, __shfl_xor_sync(0xffffffffu, rm0, 2));
            rm1 = fmaxf(rm1, __shfl_xor_sync(0xffffffffu, rm1, 1));
            rm1 = fmaxf(rm1, __shfl_xor_sync(0xffffffffu, rm1, 2));
            if (tig == 0) {
                mPart[wh * 64 + r0] = rm0;
                mPart[wh * 64 + r1] = rm1;
            }

            float rs0 = 0.f, rs1 = 0.f;
#pragma unroll
            for (int nt = 0; nt < 4; nt++) {
                float p0 = exp2f(sacc[nt][0] - rm0);
                float p1 = exp2f(sacc[nt][1] - rm0);
                float p2 = exp2f(sacc[nt][2] - rm1);
                float p3 = exp2f(sacc[nt][3] - rm1);
                sacc[nt][0] = p0; sacc[nt][1] = p1;
                sacc[nt][2] = p2; sacc[nt][3] = p3;
                rs0 += p0 + p1; rs1 += p2 + p3;
            }
            rs0 += __shfl_xor_sync(0xffffffffu, rs0, 1);
            rs0 += __shfl_xor_sync(0xffffffffu, rs0, 2);
            rs1 += __shfl_xor_sync(0xffffffffu, rs1, 1);
            rs1 += __shfl_xor_sync(0xffffffffu, rs1, 2);
            if (tig == 0) {
                sPart[wh * 64 + r0] = rs0;
                sPart[wh * 64 + r1] = rs1;
            }
            __syncthreads();

            if (kt < qt) {
                kv_issue256(sb + AKV0 + (uint32_t)(((kt + 1) & 1) * KVBUF),
                            batchbase + (size_t)(kt + 1) * 64 * H_, tid);
                CP_COMMIT();
            }

            const float rmA0 = mPart[r0], rmB0 = mPart[64 + r0];
            const float rmA1 = mPart[r1], rmB1 = mPart[64 + r1];
            const float mn0 = fmaxf(m0, fmaxf(rmA0, rmB0));
            const float mn1 = fmaxf(m1, fmaxf(rmA1, rmB1));
            const float corr0 = exp2f(m0 - mn0), corr1 = exp2f(m1 - mn1);
            l0 = l0 * corr0 + sPart[r0]      * exp2f(rmA0 - mn0)
                            + sPart[64 + r0] * exp2f(rmB0 - mn0);
            l1 = l1 * corr1 + sPart[r1]      * exp2f(rmA1 - mn1)
                            + sPart[64 + r1] * exp2f(rmB1 - mn1);
            m0 = mn0; m1 = mn1;
            const float fac0 = exp2f(rm0 - mn0);
            const float fac1 = exp2f(rm1 - mn1);

#pragma unroll
            for (int t = 0; t < 16; t++) {
                oacc[t][0] *= corr0; oacc[t][1] *= corr0;
                oacc[t][2] *= corr1; oacc[t][3] *= corr1;
            }

            uint32_t ph[2][4];
#pragma unroll
            for (int c = 0; c < 2; c++) {
#pragma unroll
                for (int half = 0; half < 2; half++) {
                    const int nt = 2 * c + half;
                    ph[c][2 * half] =
                        pack_h2(sacc[nt][0] * fac0, sacc[nt][1] * fac0);
                    ph[c][2 * half + 1] =
                        pack_h2(sacc[nt][2] * fac1, sacc[nt][3] * fac1);
                }
            }

#pragma unroll
            for (int c = 0; c < 2; c++) {
                const uint32_t roff = (uint32_t)(((wh * 2 + c) * 16 + rk) * 256);
#pragma unroll
                for (int jp = 0; jp < 8; jp++) {
                    const int gq = jp * 2 + b3;
                    const uint32_t off = roff + (uint32_t)((gq ^ xr7) << 4);
                    uint32_t t0, t1, t2, t3;
                    LDSM4T(t0, t1, t2, t3, kvb + 16384 + off);
                    uint32_t vh0[2] = {t0, t2}, vh1[2] = {t1, t3};
                    MMA16816H(oacc[2 * jp],     ph[c], vh0);
                    MMA16816H(oacc[2 * jp + 1], ph[c], vh1);
                }
            }
        }

        __syncthreads();
        if (wh == 1) {
            float* buf = (float*)(smA + AKV0 + wr * 8192);
#pragma unroll
            for (int t = 0; t < 16; t++) {
                const int col = t * 8 + tig * 2;
                *(float2*)&buf[g4 * 128 + col] =
                    make_float2(oacc[t][0], oacc[t][1]);
                *(float2*)&buf[(g4 + 8) * 128 + col] =
                    make_float2(oacc[t][2], oacc[t][3]);
            }
        }
        __syncthreads();
        if (wh == 0) {
            const float* buf = (const float*)(smA + AKV0 + wr * 8192);
            const float inv0 = 1.f / l0, inv1 = 1.f / l1;
#pragma unroll
            for (int t = 0; t < 16; t++) {
                const int col = t * 8 + tig * 2;
                float2 p0 = *(const float2*)&buf[g4 * 128 + col];
                float2 p1 = *(const float2*)&buf[(g4 + 8) * 128 + col];
                *(float2*)(out + qbase + (size_t)r0 * H_ + col) =
                    make_float2((oacc[t][0] + p0.x) * inv0,
                                (oacc[t][1] + p0.y) * inv0);
                *(float2*)(out + qbase + (size_t)r1 * H_ + col) =
                    make_float2((oacc[t][2] + p1.x) * inv1,
                                (oacc[t][3] + p1.y) * inv1);
            }
        }
    }
}

// ---------------------------------------------------------------------------
extern "C" void kernel_launch(void* const* d_in, const int* in_sizes, int n_in,
                              void* d_out, int out_size)
{
    const float* x  = (const float*)d_in[0];
    const float* Wq = (const float*)d_in[1];
    const float* Wk = (const float*)d_in[2];
    const float* Wv = (const float*)d_in[3];
    float* out = (float*)d_out;

    prep_kernel<<<4480, 256>>>(x, Wq, Wk, Wv);

    cudaFuncSetAttribute(qkv_mma_kernel,
                         cudaFuncAttributeMaxDynamicSharedMemorySize, QK_SMEM);
    qkv_mma_kernel<<<dim3(6, 128), 256, QK_SMEM>>>();

    cudaFuncSetAttribute(attn_mma_kernel,
                         cudaFuncAttributeMaxDynamicSharedMemorySize, ATT_SMEM);
    attn_mma_kernel<<<dim3(16, 8), 256, ATT_SMEM>>>(out);
}